// round 9
// baseline (speedup 1.0000x reference)
#include <cuda_runtime.h>
#include <cstdint>

#define W 512
#define H 512
#define PLANES 48
#define TX 64          // output tile width
#define TY 32          // output tile height
#define HALO 5
#define NCOL 74        // TX + 2*HALO columns of intermediates
#define PSTRIDE 74     // u64 stride (148 words ≡ 20 mod 32 -> conflict-free 16B loads)
#define NTH 320

// staged raw tile: 42 rows x 80 cols per image (16B-aligned rows)
#define SROWS 42
#define SCOLS 80
#define SIMG  (SROWS * SCOLS)          // floats per image = 3360
#define NCHUNK (SROWS * (SCOLS/4) * 2) // 16B chunks to stage = 1680

#define OFF_RAW 0
#define OFF_VHV (SIMG * 2 * 4)                         // 26880
#define OFF_VHZ (OFF_VHV + TY * PSTRIDE * 8)           // 45824
#define OFF_WP  (OFF_VHZ + TY * PSTRIDE * 8)           // 64768
#define SMEM_TOTAL (OFF_WP + 64)                       // 64832

typedef unsigned long long u64;

__device__ double g_accum;
__device__ unsigned int g_count;

// Gaussian taps exp(-d^2/4.5), normalized in double at compile time.
#define E0d 1.0
#define E1d 0.8007374029168081
#define E2d 0.4111122905071874
#define E3d 0.1353352832366127
#define E4d 0.0285655007845531
#define E5d 0.0038659201394728
#define ESd (E0d + 2.0*(E1d+E2d+E3d+E4d+E5d))
#define GW0 ((float)(E5d/ESd))
#define GW1 ((float)(E4d/ESd))
#define GW2 ((float)(E3d/ESd))
#define GW3 ((float)(E2d/ESd))
#define GW4 ((float)(E1d/ESd))
#define GW5 ((float)(E0d/ESd))

__device__ __forceinline__ u64 pack2(float a, float b) {
    u64 r; asm("mov.b64 %0, {%1, %2};" : "=l"(r) : "f"(a), "f"(b)); return r;
}
__device__ __forceinline__ void unpack2(u64 v, float& a, float& b) {
    asm("mov.b64 {%0, %1}, %2;" : "=f"(a), "=f"(b) : "l"(v));
}
__device__ __forceinline__ u64 fma2(u64 a, u64 b, u64 c) {
    u64 d; asm("fma.rn.f32x2 %0, %1, %2, %3;" : "=l"(d) : "l"(a), "l"(b), "l"(c)); return d;
}
__device__ __forceinline__ uint32_t smem_u32(const void* p) {
    return (uint32_t)__cvta_generic_to_shared(p);
}
__device__ __forceinline__ void cp_async16(uint32_t dst, const void* src) {
    asm volatile("cp.async.ca.shared.global [%0], [%1], 16;" :: "r"(dst), "l"(src));
}

// ---- Phase A conv core (shared by both input paths) ------------------------
struct AccAZ { u64 aV[8]; u64 aZ[8]; };

__device__ __forceinline__ void chainsStep(AccAZ& A, float x, float y, int j,
                                           const u64* gw2) {
    const u64 v  = pack2(x, y);
    const float xy = x * y;
    const float z  = fmaf(y, y, x * x);
    const u64 zc = pack2(z, xy);
#pragma unroll
    for (int i = 0; i < 8; i++) {
        const int k = j - i;
        if (k >= 0 && k < 11) {
            const int ks = (k < 10 - k) ? k : (10 - k);
            A.aV[i] = fma2(gw2[ks], v,  A.aV[i]);
            A.aZ[i] = fma2(gw2[ks], zc, A.aZ[i]);
        }
    }
}

// Phase A from staged smem tile (interior blocks).
__device__ __forceinline__ void phaseA_smem(const float* __restrict__ sraw,
                                            int tid,
                                            u64 (*vhV)[PSTRIDE], u64 (*vhZ)[PSTRIDE],
                                            const u64* gw2) {
    const int gi = tid / NCOL;
    const int cc = tid - gi * NCOL;
    const float* rx = sraw +         gi * 8 * SCOLS + (cc + 3);
    const float* ry = sraw + SIMG +  gi * 8 * SCOLS + (cc + 3);

    AccAZ A;
#pragma unroll
    for (int i = 0; i < 8; i++) { A.aV[i] = 0ull; A.aZ[i] = 0ull; }

#pragma unroll
    for (int j = 0; j < 18; j++) {
        const float x = rx[j * SCOLS];
        const float y = ry[j * SCOLS];
        chainsStep(A, x, y, j, gw2);
    }
    const int r0 = gi * 8;
#pragma unroll
    for (int i = 0; i < 8; i++) {
        vhV[r0 + i][cc] = A.aV[i];
        vhZ[r0 + i][cc] = A.aZ[i];
    }
}

// Phase A with border guards, straight from global (border blocks).
__device__ __forceinline__ void phaseA_guard(const float* __restrict__ p1,
                                             const float* __restrict__ p2,
                                             int row0, int col0, int tid,
                                             u64 (*vhV)[PSTRIDE], u64 (*vhZ)[PSTRIDE],
                                             const u64* gw2) {
    const int gi = tid / NCOL;
    const int cc = tid - gi * NCOL;
    const int gc = col0 + cc - HALO;
    const int rbase = row0 + gi * 8 - HALO;
    const bool colOk = ((unsigned)gc < (unsigned)W);

    AccAZ A;
#pragma unroll
    for (int i = 0; i < 8; i++) { A.aV[i] = 0ull; A.aZ[i] = 0ull; }

#pragma unroll
    for (int j = 0; j < 18; j++) {
        const int gr = rbase + j;
        float x = 0.f, y = 0.f;
        if (colOk && (unsigned)gr < (unsigned)H) {
            const int off = gr * W + gc;
            x = p1[off];
            y = p2[off];
        }
        chainsStep(A, x, y, j, gw2);
    }
    const int r0 = gi * 8;
#pragma unroll
    for (int i = 0; i < 8; i++) {
        vhV[r0 + i][cc] = A.aV[i];
        vhZ[r0 + i][cc] = A.aZ[i];
    }
}

__launch_bounds__(NTH, 3)
__global__ void ssim_fused(const float* __restrict__ img1,
                           const float* __restrict__ img2,
                           float* __restrict__ out) {
    extern __shared__ __align__(16) char smem[];
    float* sraw = (float*)(smem + OFF_RAW);
    u64 (*vhV)[PSTRIDE] = (u64(*)[PSTRIDE])(smem + OFF_VHV);
    u64 (*vhZ)[PSTRIDE] = (u64(*)[PSTRIDE])(smem + OFF_VHZ);
    float* wpart = (float*)(smem + OFF_WP);

    u64 gw2[6];
    {
        const float gwv[6] = {GW0, GW1, GW2, GW3, GW4, GW5};
#pragma unroll
        for (int k = 0; k < 6; k++) gw2[k] = pack2(gwv[k], gwv[k]);
    }

    const int tid   = threadIdx.x;
    const int plane = blockIdx.z;
    const int row0  = blockIdx.y * TY;
    const int col0  = blockIdx.x * TX;
    const float* p1 = img1 + (size_t)plane * (W * H);
    const float* p2 = img2 + (size_t)plane * (W * H);

    const bool interior = (row0 >= HALO) && (row0 + TY + HALO <= H) &&
                          (col0 >= 8)    && (col0 + TX + 8 <= W);

    // ---------------- Phase A ------------------------------------------------
    if (interior) {
        // stage raw tile (42 x 80 x 2 images) via cp.async, all threads
        const int base_row = row0 - HALO;
        const int base_col = col0 - 8;
        const float* s1 = p1 + base_row * W + base_col;
        const float* s2 = p2 + base_row * W + base_col;
#pragma unroll
        for (int it = 0; it < 6; it++) {
            const int ch = tid + it * NTH;
            if (ch < NCHUNK) {
                const int img = (ch >= NCHUNK / 2);
                const int rem = img ? ch - NCHUNK / 2 : ch;
                const int row = rem / (SCOLS / 4);
                const int c4  = rem - row * (SCOLS / 4);
                const float* src = (img ? s2 : s1) + row * W + c4 * 4;
                const uint32_t dst = smem_u32(sraw + img * SIMG + row * SCOLS + c4 * 4);
                cp_async16(dst, src);
            }
        }
        asm volatile("cp.async.commit_group;");
        asm volatile("cp.async.wait_group 0;" ::: "memory");
        __syncthreads();
        if (tid < 4 * NCOL)
            phaseA_smem(sraw, tid, vhV, vhZ, gw2);
    } else {
        if (tid < 4 * NCOL)
            phaseA_guard(p1, p2, row0, col0, tid, vhV, vhZ, gw2);
    }
    __syncthreads();

    // ---------------- Phase B: horizontal pass + SSIM -----------------------
    float local = 0.f;
    if (tid < 256) {
        const int r  = tid & 31;
        const int c0 = (tid >> 5) * 8;

        const float C1 = 1e-4f;
        const float C2 = 9e-4f;
        const float C2E = C2 + 1e-6f;

        // -- pass 1: V = (mu1, mu2) packed --
        u64 mV[8];
        {
            u64 fV[18];
            const ulonglong2* rp = reinterpret_cast<const ulonglong2*>(&vhV[r][c0]);
#pragma unroll
            for (int v = 0; v < 9; v++) { ulonglong2 t = rp[v]; fV[2*v] = t.x; fV[2*v+1] = t.y; }
#pragma unroll
            for (int i = 0; i < 8; i++) {
                u64 acc = 0ull;
#pragma unroll
                for (int k = 0; k < 11; k++) {
                    const int ks = (k < 10 - k) ? k : (10 - k);
                    acc = fma2(gw2[ks], fV[i + k], acc);
                }
                mV[i] = acc;
            }
        }

        // -- pass 2: Z = (conv(x2+y2), conv(xy)); finish SSIM --
        {
            u64 fZ[18];
            const ulonglong2* rp = reinterpret_cast<const ulonglong2*>(&vhZ[r][c0]);
#pragma unroll
            for (int v = 0; v < 9; v++) { ulonglong2 t = rp[v]; fZ[2*v] = t.x; fZ[2*v+1] = t.y; }
#pragma unroll
            for (int i = 0; i < 8; i++) {
                u64 acc = 0ull;
#pragma unroll
                for (int k = 0; k < 11; k++) {
                    const int ks = (k < 10 - k) ? k : (10 - k);
                    acc = fma2(gw2[ks], fZ[i + k], acc);
                }
                float mu1, mu2, z, mxy;
                unpack2(mV[i], mu1, mu2);
                unpack2(acc,   z,   mxy);
                const float musq = fmaf(mu1, mu1, mu2 * mu2);
                const float mu12 = mu1 * mu2;
                const float ssum = z   - musq;
                const float s12  = mxy - mu12;
                const float num = fmaf(2.f, mu12, C1) * fmaf(2.f, s12, C2);
                const float den = (musq + C1) * (ssum + C2E);
                local += __fdividef(num, den);
            }
        }
    }

    // ---------------- Reduction ----------------------------------------------
#pragma unroll
    for (int off = 16; off > 0; off >>= 1)
        local += __shfl_down_sync(0xffffffffu, local, off);
    if ((tid & 31) == 0) wpart[tid >> 5] = local;
    __syncthreads();
    if (tid == 0) {
        float bs = 0.f;
#pragma unroll
        for (int wv = 0; wv < NTH / 32; wv++) bs += wpart[wv];
        atomicAdd(&g_accum, (double)bs);
        __threadfence();
        const unsigned total = gridDim.x * gridDim.y * gridDim.z;
        if (atomicAdd(&g_count, 1u) == total - 1) {
            const double acc = atomicAdd(&g_accum, 0.0);
            out[0] = (float)(acc / ((double)PLANES * (double)W * (double)H));
            g_accum = 0.0;   // reset so every graph replay is identical
            g_count = 0u;
        }
    }
}

extern "C" void kernel_launch(void* const* d_in, const int* in_sizes, int n_in,
                              void* d_out, int out_size) {
    const float* img1 = (const float*)d_in[0];
    const float* img2 = (const float*)d_in[1];
    float* out = (float*)d_out;

    static bool attr_set = false;
    if (!attr_set) {
        cudaFuncSetAttribute(ssim_fused,
                             cudaFuncAttributeMaxDynamicSharedMemorySize,
                             SMEM_TOTAL);
        attr_set = true;
    }

    dim3 grid(W / TX, H / TY, PLANES);
    ssim_fused<<<grid, NTH, SMEM_TOTAL>>>(img1, img2, out);
}